// round 15
// baseline (speedup 1.0000x reference)
#include <cuda_runtime.h>
#include <math.h>

#define TSEQ 500
#define BATCH 512

typedef unsigned long long u64;

__device__ __forceinline__ void ffma2(u64& d, u64 a, u64 b, u64 c) {
    asm("fma.rn.f32x2 %0, %1, %2, %3;" : "=l"(d) : "l"(a), "l"(b), "l"(c));
}
__device__ __forceinline__ u64 fmul2(u64 a, u64 b) {
    u64 d; asm("mul.rn.f32x2 %0, %1, %2;" : "=l"(d) : "l"(a), "l"(b)); return d;
}
__device__ __forceinline__ u64 fadd2(u64 a, u64 b) {
    u64 d; asm("add.rn.f32x2 %0, %1, %2;" : "=l"(d) : "l"(a), "l"(b)); return d;
}
__device__ __forceinline__ float2 up2(u64 v) {
    float2 f; asm("mov.b64 {%0,%1}, %2;" : "=f"(f.x), "=f"(f.y) : "l"(v)); return f;
}
__device__ __forceinline__ u64 pk2(float x, float y) {
    u64 v; asm("mov.b64 %0, {%1,%2};" : "=l"(v) : "f"(x), "f"(y)); return v;
}

// ONE WARP PER BATCH, K=4 blocked updates, ZERO block-level barriers.
// lane = rg*4 + cg; rg in [0,8): rows 8rg..8rg+7; cg in [0,4): cols 16cg..16cg+15.
// Thread owns P[8][16] as P2[8][8] packed f32x2 (128 regs).
// mu col strip (16) in registers, replicated across the 8 rg groups.
// Per 4-obs block: V = P H4^T (4 independent 2-round reduce-scatters),
// Gram(10)+z(4) via one 16-value/16-lane butterfly, ONE __syncwarp,
// K-space recursion in registers, rank-4 register update.

__global__ void __launch_bounds__(128, 1)
akf_main(const float* __restrict__ ext, const float* __restrict__ obs,
         const float* __restrict__ mu0, const float* __restrict__ sg0,
         const float* __restrict__ lsig, const float* __restrict__ Bm,
         const float* __restrict__ Hm, const float* __restrict__ ldel,
         float* __restrict__ out)
{
    __shared__ __align__(16) float sh_H[4096];
    __shared__ __align__(16) float sh_B[2048];
    __shared__ __align__(16) float sh_V[4][2][4][64];   // [warp][pb][j][row]
    __shared__ __align__(16) float sh_G[4][2][16];
    __shared__ __align__(16) float sh_y[4][2][64];
    __shared__ __align__(16) float sh_u[4][2][32];
    __shared__ float sh_r[64], sh_q[64];

    const int tid  = threadIdx.x;
    const int w    = tid >> 5;
    const int lane = tid & 31;
    const int b    = (blockIdx.x << 2) | w;
    const int rg   = lane >> 2;
    const int cg   = lane & 3;
    const int r0   = rg << 3;     // my 8 rows
    const int c0   = cg << 4;     // my 16 cols
    const bool diag  = (cg == (rg >> 1));
    const int  dbase = (rg & 1) << 3;
    const bool bb0 = cg & 1, bb1 = cg & 2;
    const int  vidx = ((cg & 1) << 2) | (cg & 2);   // 4*bit0 + 2*bit1

    for (int i = tid; i < 4096; i += 128) sh_H[i] = Hm[i];
    for (int i = tid; i < 2048; i += 128) sh_B[i] = Bm[i];
    if (tid < 64) {
        float e = expf(ldel[tid]); sh_r[tid] = e * e;
        float f = expf(lsig[tid]); sh_q[tid] = f * f;
    }

    u64 P2[8][8];
    #pragma unroll
    for (int a = 0; a < 8; ++a)
        #pragma unroll
        for (int m = 0; m < 8; ++m) P2[a][m] = 0ull;

    float* outmu = out;
    float* outls = out + (size_t)TSEQ * BATCH * 64;

    // mu col strip (16 floats packed), replicated across rg
    u64 muc2[8];
    {
        const float* mp = &mu0[b * 64 + c0];
        #pragma unroll
        for (int p = 0; p < 8; ++p) muc2[p] = pk2(mp[2 * p], mp[2 * p + 1]);
    }
    if (diag) {
        #pragma unroll
        for (int a = 0; a < 8; ++a) {
            float s0v = sg0[b * 64 + r0 + a];
            int m = (dbase + a) >> 1;
            float2 e = up2(P2[a][m]);
            if (a & 1) e.y = s0v * s0v; else e.x = s0v * s0v;
            P2[a][m] = pk2(e.x, e.y);
        }
        #pragma unroll
        for (int a = 0; a < 8; ++a)
            outls[b * 64 + r0 + a] = logf(sg0[b * 64 + r0 + a]);
    }
    if (rg == 0) {
        #pragma unroll
        for (int j = 0; j < 16; ++j)
            outmu[b * 64 + c0 + j] = mu0[b * 64 + c0 + j];
    }
    // stage y/u for t=1 (parity 1)
    {
        float2 yv = *(const float2*)&obs[((size_t)1 * BATCH + b) * 64 + 2 * lane];
        *(float2*)&sh_y[w][1][2 * lane] = yv;
        sh_u[w][1][lane] = ext[((size_t)0 * BATCH + b) * 32 + lane];
    }
    __syncthreads();

    for (int t = 1; t < TSEQ; ++t) {
        const int tb = t & 1;

        // ---- predict: muc += B u (my 16 cols) ; P += diag(q) ----
        {
            u64 uu[16];
            const ulonglong2* up = (const ulonglong2*)&sh_u[w][tb][0];
            #pragma unroll
            for (int m = 0; m < 8; ++m) { ulonglong2 v = up[m]; uu[2*m] = v.x; uu[2*m+1] = v.y; }
            #pragma unroll
            for (int p = 0; p < 8; ++p) {
                float d[2];
                #pragma unroll
                for (int e = 0; e < 2; ++e) {
                    const ulonglong2* Bp = (const ulonglong2*)&sh_B[(c0 + 2*p + e) * 32];
                    u64 acc = 0ull;
                    #pragma unroll
                    for (int m = 0; m < 8; ++m) {
                        ulonglong2 bb = Bp[m];
                        ffma2(acc, bb.x, uu[2*m], acc);
                        ffma2(acc, bb.y, uu[2*m+1], acc);
                    }
                    float2 f = up2(acc); d[e] = f.x + f.y;
                }
                muc2[p] = fadd2(muc2[p], pk2(d[0], d[1]));
            }
        }
        if (diag) {
            #pragma unroll
            for (int a = 0; a < 8; ++a) {
                float qv = sh_q[r0 + a];
                int m = (dbase + a) >> 1;
                float2 e = up2(P2[a][m]);
                if (a & 1) e.y += qv; else e.x += qv;
                P2[a][m] = pk2(e.x, e.y);
            }
        }

        // prefetch next step's y/u into registers
        const int tn = (t + 1 < TSEQ) ? t + 1 : t;
        float2 ry2 = *(const float2*)&obs[((size_t)tn * BATCH + b) * 64 + 2 * lane];
        float  ru  = ext[((size_t)(tn - 1) * BATCH + b) * 32 + lane];

        // ---- 16 blocks of 4 observations, ONE __syncwarp each ----
        #pragma unroll 1
        for (int blk = 0; blk < 16; ++blk) {
            const int o  = blk << 2;
            const int pb = blk & 1;

            // phase 1: vp partials, V reduce-scatter, z partials
            float vp[4][8];
            float zz[4];
            #pragma unroll
            for (int j = 0; j < 4; ++j) {
                const ulonglong2* hp = (const ulonglong2*)&sh_H[((o + j) << 6) + c0];
                u64 h2[8];
                #pragma unroll
                for (int m = 0; m < 4; ++m) { ulonglong2 hv = hp[m]; h2[2*m] = hv.x; h2[2*m+1] = hv.y; }
                #pragma unroll
                for (int a = 0; a < 8; ++a) {
                    u64 acc = 0ull;
                    #pragma unroll
                    for (int m = 0; m < 8; ++m) ffma2(acc, P2[a][m], h2[m], acc);
                    float2 f = up2(acc);
                    vp[j][a] = f.x + f.y;
                }
                // reduce-scatter 8 values over 4 lanes (2 rounds, 6 shfl)
                float k4[4], k2[2];
                #pragma unroll
                for (int m = 0; m < 4; ++m) {
                    float keep = bb0 ? vp[j][m + 4] : vp[j][m];
                    float send = bb0 ? vp[j][m]     : vp[j][m + 4];
                    k4[m] = keep + __shfl_xor_sync(0xffffffffu, send, 1);
                }
                #pragma unroll
                for (int m = 0; m < 2; ++m) {
                    float keep = bb1 ? k4[m + 2] : k4[m];
                    float send = bb1 ? k4[m]     : k4[m + 2];
                    k2[m] = keep + __shfl_xor_sync(0xffffffffu, send, 2);
                }
                *(float2*)&sh_V[w][pb][j][r0 + vidx] = make_float2(k2[0], k2[1]);
                // z partial over my 16 cols (identical across the 8 rg copies)
                u64 za = 0ull;
                #pragma unroll
                for (int m = 0; m < 8; ++m) ffma2(za, h2[m], muc2[m], za);
                float2 zf = up2(za);
                zz[j] = zf.x + zf.y;
            }

            // phase 1b: Gram partials + 16-value/16-lane butterfly
            {
                u64 vpp[4][4];
                #pragma unroll
                for (int k = 0; k < 4; ++k)
                    #pragma unroll
                    for (int m = 0; m < 4; ++m)
                        vpp[k][m] = pk2(vp[k][2 * m], vp[k][2 * m + 1]);
                u64 hq2[4][4];
                #pragma unroll
                for (int j = 0; j < 4; ++j) {
                    const ulonglong2* hr = (const ulonglong2*)&sh_H[((o + j) << 6) + r0];
                    ulonglong2 ha = hr[0], hb = hr[1];
                    hq2[j][0] = ha.x; hq2[j][1] = ha.y; hq2[j][2] = hb.x; hq2[j][3] = hb.y;
                }
                #define GD(j, k) ({ u64 acc = 0ull; \
                    ffma2(acc, hq2[j][0], vpp[k][0], acc); \
                    ffma2(acc, hq2[j][1], vpp[k][1], acc); \
                    ffma2(acc, hq2[j][2], vpp[k][2], acc); \
                    ffma2(acc, hq2[j][3], vpp[k][3], acc); \
                    float2 f = up2(acc); f.x + f.y; })
                float val[16];
                val[0] = GD(0, 0); val[1] = GD(1, 0); val[2] = GD(1, 1);
                val[3] = GD(2, 0); val[4] = GD(2, 1); val[5] = GD(2, 2);
                val[6] = GD(3, 0); val[7] = GD(3, 1); val[8] = GD(3, 2);
                val[9] = GD(3, 3);
                #undef GD
                val[10] = zz[0]; val[11] = zz[1]; val[12] = zz[2]; val[13] = zz[3];
                val[14] = 0.0f;  val[15] = 0.0f;

                const bool s3 = lane & 8, s2l = lane & 4, s1 = lane & 2, s0 = lane & 1;
                #pragma unroll
                for (int k = 0; k < 8; ++k) {
                    float keep = s3 ? val[k + 8] : val[k];
                    float send = s3 ? val[k]     : val[k + 8];
                    val[k] = keep + __shfl_xor_sync(0xffffffffu, send, 8);
                }
                #pragma unroll
                for (int k = 0; k < 4; ++k) {
                    float keep = s2l ? val[k + 4] : val[k];
                    float send = s2l ? val[k]     : val[k + 4];
                    val[k] = keep + __shfl_xor_sync(0xffffffffu, send, 4);
                }
                #pragma unroll
                for (int k = 0; k < 2; ++k) {
                    float keep = s1 ? val[k + 2] : val[k];
                    float send = s1 ? val[k]     : val[k + 2];
                    val[k] = keep + __shfl_xor_sync(0xffffffffu, send, 2);
                }
                {
                    float keep = s0 ? val[1] : val[0];
                    float send = s0 ? val[0] : val[1];
                    val[0] = keep + __shfl_xor_sync(0xffffffffu, send, 1);
                }
                val[0] += __shfl_xor_sync(0xffffffffu, val[0], 16);
                if (lane < 14) sh_G[w][pb][lane] = val[0];
            }
            __syncwarp();   // the ONLY sync per block

            // phase 3: K-space recursion (redundant per lane, exact)
            float4 ga = *(const float4*)&sh_G[w][pb][0];   // g00 u01 g11 u02
            float4 gb = *(const float4*)&sh_G[w][pb][4];   // g21 g22 u03 g31
            float4 gc = *(const float4*)&sh_G[w][pb][8];   // g32 g33 z0 z1
            float2 gd = *(const float2*)&sh_G[w][pb][12];  // z2 z3
            float4 yq = *(const float4*)&sh_y[w][tb][o];
            float z0 = gc.z * 0.125f, z1 = gc.w * 0.125f;
            float z2 = gd.x * 0.125f, z3 = gd.y * 0.125f;

            float rs0 = __fdividef(1.0f, ga.x + sh_r[o + 0]);
            float c01 = ga.y * rs0, c02 = ga.w * rs0, c03 = gb.z * rs0;
            float u12 = gb.x - c01 * ga.w;
            float u13 = gb.w - c01 * gb.z;
            float rs1 = __fdividef(1.0f, (ga.z - c01 * ga.y) + sh_r[o + 1]);
            float c12 = u12 * rs1, c13 = u13 * rs1;
            float u23 = gc.x - c02 * gb.z - c12 * u13;
            float rs2 = __fdividef(1.0f, (gb.y - c02 * ga.w - c12 * u12) + sh_r[o + 2]);
            float c23 = u23 * rs2;
            float rs3 = __fdividef(1.0f, (gc.y - c03 * gb.z - c13 * u13 - c23 * u23) + sh_r[o + 3]);
            float f0 = (yq.x - z0) * rs0;
            float f1 = (yq.y - z1 - ga.y * f0) * rs1;
            float f2 = (yq.z - z2 - ga.w * f0 - u12 * f1) * rs2;
            float f3 = (yq.w - z3 - gb.z * f0 - u13 * f1 - u23 * f2) * rs3;

            // phase 4: w col strips, mu update, pre-scale, w row strips, rank-4
            u64 wc[4][8];
            #pragma unroll
            for (int i = 0; i < 4; ++i) {
                const ulonglong2* vq = (const ulonglong2*)&sh_V[w][pb][i][c0];
                #pragma unroll
                for (int m = 0; m < 4; ++m) {
                    ulonglong2 vv = vq[m];
                    wc[i][2*m] = vv.x; wc[i][2*m+1] = vv.y;
                }
            }
            {
                u64 n01 = pk2(-c01, -c01), n02 = pk2(-c02, -c02), n03 = pk2(-c03, -c03);
                u64 n12 = pk2(-c12, -c12), n13 = pk2(-c13, -c13), n23 = pk2(-c23, -c23);
                #pragma unroll
                for (int m = 0; m < 8; ++m) {
                    ffma2(wc[1][m], n01, wc[0][m], wc[1][m]);
                    ffma2(wc[2][m], n02, wc[0][m], wc[2][m]);
                    ffma2(wc[2][m], n12, wc[1][m], wc[2][m]);
                    ffma2(wc[3][m], n03, wc[0][m], wc[3][m]);
                    ffma2(wc[3][m], n13, wc[1][m], wc[3][m]);
                    ffma2(wc[3][m], n23, wc[2][m], wc[3][m]);
                }
            }
            {
                u64 f02 = pk2(f0, f0), f12 = pk2(f1, f1);
                u64 f22 = pk2(f2, f2), f32 = pk2(f3, f3);
                #pragma unroll
                for (int m = 0; m < 8; ++m) {
                    ffma2(muc2[m], f02, wc[0][m], muc2[m]);
                    ffma2(muc2[m], f12, wc[1][m], muc2[m]);
                    ffma2(muc2[m], f22, wc[2][m], muc2[m]);
                    ffma2(muc2[m], f32, wc[3][m], muc2[m]);
                }
            }
            {
                u64 m0s = pk2(-rs0, -rs0), m1s = pk2(-rs1, -rs1);
                u64 m2s = pk2(-rs2, -rs2), m3s = pk2(-rs3, -rs3);
                #pragma unroll
                for (int m = 0; m < 8; ++m) {
                    wc[0][m] = fmul2(wc[0][m], m0s);
                    wc[1][m] = fmul2(wc[1][m], m1s);
                    wc[2][m] = fmul2(wc[2][m], m2s);
                    wc[3][m] = fmul2(wc[3][m], m3s);
                }
            }
            float wr[4][8];
            #pragma unroll
            for (int i = 0; i < 4; ++i) {
                float4 pa = *(const float4*)&sh_V[w][pb][i][r0];
                float4 pe = *(const float4*)&sh_V[w][pb][i][r0 + 4];
                wr[i][0]=pa.x; wr[i][1]=pa.y; wr[i][2]=pa.z; wr[i][3]=pa.w;
                wr[i][4]=pe.x; wr[i][5]=pe.y; wr[i][6]=pe.z; wr[i][7]=pe.w;
            }
            #pragma unroll
            for (int a = 0; a < 8; ++a) {
                wr[1][a] -= c01 * wr[0][a];
                wr[2][a] -= c02 * wr[0][a] + c12 * wr[1][a];
                wr[3][a] -= c03 * wr[0][a] + c13 * wr[1][a] + c23 * wr[2][a];
            }
            #pragma unroll
            for (int a = 0; a < 8; ++a) {
                #pragma unroll
                for (int i = 0; i < 4; ++i) {
                    u64 g = pk2(wr[i][a], wr[i][a]);
                    #pragma unroll
                    for (int m = 0; m < 8; ++m)
                        ffma2(P2[a][m], g, wc[i][m], P2[a][m]);
                }
            }
        }

        // ---- outputs ; stage next step's y/u ----
        if (rg == 0) {
            float* op = &outmu[((size_t)t * BATCH + b) * 64 + c0];
            #pragma unroll
            for (int p = 0; p < 4; ++p) {
                float2 e0 = up2(muc2[2 * p]), e1 = up2(muc2[2 * p + 1]);
                *(float4*)(op + 4 * p) = make_float4(e0.x, e0.y, e1.x, e1.y);
            }
        }
        if (diag) {
            #pragma unroll
            for (int a = 0; a < 8; ++a) {
                float2 e = up2(P2[a][(dbase + a) >> 1]);
                float dv = (a & 1) ? e.y : e.x;
                outls[((size_t)t * BATCH + b) * 64 + r0 + a] = 0.5f * logf(dv);
            }
        }
        *(float2*)&sh_y[w][tb ^ 1][2 * lane] = ry2;
        sh_u[w][tb ^ 1][lane] = ru;
        __syncwarp();
    }
}

extern "C" void kernel_launch(void* const* d_in, const int* in_sizes, int n_in,
                              void* d_out, int out_size) {
    const float* ext  = (const float*)d_in[0];   // (500, 512, 32)
    const float* obs  = (const float*)d_in[1];   // (500, 512, 64)
    const float* mu0  = (const float*)d_in[2];   // (512, 64)
    const float* sg0  = (const float*)d_in[3];   // (512, 64)
    const float* lsig = (const float*)d_in[4];   // (64,)
    const float* Bm   = (const float*)d_in[5];   // (64, 32)
    const float* H    = (const float*)d_in[6];   // (64, 64)
    const float* ldel = (const float*)d_in[7];   // (64,)
    float* out = (float*)d_out;

    akf_main<<<BATCH / 4, 128>>>(ext, obs, mu0, sg0, lsig, Bm, H, ldel, out);
}

// round 16
// speedup vs baseline: 1.1291x; 1.1291x over previous
#include <cuda_runtime.h>
#include <math.h>

#define TSEQ 500
#define BATCH 512

typedef unsigned long long u64;

__device__ __forceinline__ void ffma2(u64& d, u64 a, u64 b, u64 c) {
    asm("fma.rn.f32x2 %0, %1, %2, %3;" : "=l"(d) : "l"(a), "l"(b), "l"(c));
}
__device__ __forceinline__ u64 fmul2(u64 a, u64 b) {
    u64 d; asm("mul.rn.f32x2 %0, %1, %2;" : "=l"(d) : "l"(a), "l"(b)); return d;
}
__device__ __forceinline__ u64 fadd2(u64 a, u64 b) {
    u64 d; asm("add.rn.f32x2 %0, %1, %2;" : "=l"(d) : "l"(a), "l"(b)); return d;
}
__device__ __forceinline__ float2 up2(u64 v) {
    float2 f; asm("mov.b64 {%0,%1}, %2;" : "=f"(f.x), "=f"(f.y) : "l"(v)); return f;
}
__device__ __forceinline__ u64 pk2(float x, float y) {
    u64 v; asm("mov.b64 %0, {%1,%2};" : "=l"(v) : "f"(x), "f"(y)); return v;
}

// ONE WARP PER BATCH, K=2 blocked updates, zero barriers (32 __syncwarp/step).
// lane = rg*4 + cg; rg in [0,8): rows 8rg..8rg+7; cg in [0,4): cols 16cg..16cg+15.
// Thread owns P[8][16] as P2[8][8] packed f32x2 (128 regs).
// mu col strip (16) in registers, replicated across the 8 rg groups.
// Per 2-obs block: V = P H2^T (2 reduce-scatters), Gram{3}+z{2} via one
// 8-value/9-shfl butterfly, ONE __syncwarp, 2x2 recursion, rank-2 update.

__global__ void __launch_bounds__(128, 1)
akf_main(const float* __restrict__ ext, const float* __restrict__ obs,
         const float* __restrict__ mu0, const float* __restrict__ sg0,
         const float* __restrict__ lsig, const float* __restrict__ Bm,
         const float* __restrict__ Hm, const float* __restrict__ ldel,
         float* __restrict__ out)
{
    __shared__ __align__(16) float sh_H[4096];
    __shared__ __align__(16) float sh_B[2048];
    __shared__ __align__(16) float sh_V[4][2][2][64];   // [warp][pb][j][row]
    __shared__ __align__(16) float sh_G[4][2][8];
    __shared__ __align__(16) float sh_y[4][2][64];
    __shared__ __align__(16) float sh_u[4][2][32];
    __shared__ float sh_r[64], sh_q[64];

    const int tid  = threadIdx.x;
    const int w    = tid >> 5;
    const int lane = tid & 31;
    const int b    = (blockIdx.x << 2) | w;
    const int rg   = lane >> 2;
    const int cg   = lane & 3;
    const int r0   = rg << 3;     // my 8 rows
    const int c0   = cg << 4;     // my 16 cols
    const bool diag  = (cg == (rg >> 1));
    const int  dbase = (rg & 1) << 3;
    const bool bb0 = cg & 1, bb1 = cg & 2;
    const int  vidx = ((cg & 1) << 2) | (cg & 2);

    for (int i = tid; i < 4096; i += 128) sh_H[i] = Hm[i];
    for (int i = tid; i < 2048; i += 128) sh_B[i] = Bm[i];
    if (tid < 64) {
        float e = expf(ldel[tid]); sh_r[tid] = e * e;
        float f = expf(lsig[tid]); sh_q[tid] = f * f;
    }

    u64 P2[8][8];
    #pragma unroll
    for (int a = 0; a < 8; ++a)
        #pragma unroll
        for (int m = 0; m < 8; ++m) P2[a][m] = 0ull;

    float* outmu = out;
    float* outls = out + (size_t)TSEQ * BATCH * 64;

    u64 muc2[8];
    {
        const float* mp = &mu0[b * 64 + c0];
        #pragma unroll
        for (int p = 0; p < 8; ++p) muc2[p] = pk2(mp[2 * p], mp[2 * p + 1]);
    }
    if (diag) {
        #pragma unroll
        for (int a = 0; a < 8; ++a) {
            float s0v = sg0[b * 64 + r0 + a];
            int m = (dbase + a) >> 1;
            float2 e = up2(P2[a][m]);
            if (a & 1) e.y = s0v * s0v; else e.x = s0v * s0v;
            P2[a][m] = pk2(e.x, e.y);
        }
        #pragma unroll
        for (int a = 0; a < 8; ++a)
            outls[b * 64 + r0 + a] = logf(sg0[b * 64 + r0 + a]);
    }
    if (rg == 0) {
        #pragma unroll
        for (int j = 0; j < 16; ++j)
            outmu[b * 64 + c0 + j] = mu0[b * 64 + c0 + j];
    }
    {
        float2 yv = *(const float2*)&obs[((size_t)1 * BATCH + b) * 64 + 2 * lane];
        *(float2*)&sh_y[w][1][2 * lane] = yv;
        sh_u[w][1][lane] = ext[((size_t)0 * BATCH + b) * 32 + lane];
    }
    __syncthreads();

    for (int t = 1; t < TSEQ; ++t) {
        const int tb = t & 1;

        // ---- predict: muc += B u (my 16 cols) ; P += diag(q) ----
        {
            u64 uu[16];
            const ulonglong2* up = (const ulonglong2*)&sh_u[w][tb][0];
            #pragma unroll
            for (int m = 0; m < 8; ++m) { ulonglong2 v = up[m]; uu[2*m] = v.x; uu[2*m+1] = v.y; }
            #pragma unroll
            for (int p = 0; p < 8; ++p) {
                float d[2];
                #pragma unroll
                for (int e = 0; e < 2; ++e) {
                    const ulonglong2* Bp = (const ulonglong2*)&sh_B[(c0 + 2*p + e) * 32];
                    u64 acc = 0ull;
                    #pragma unroll
                    for (int m = 0; m < 8; ++m) {
                        ulonglong2 bb = Bp[m];
                        ffma2(acc, bb.x, uu[2*m], acc);
                        ffma2(acc, bb.y, uu[2*m+1], acc);
                    }
                    float2 f = up2(acc); d[e] = f.x + f.y;
                }
                muc2[p] = fadd2(muc2[p], pk2(d[0], d[1]));
            }
        }
        if (diag) {
            #pragma unroll
            for (int a = 0; a < 8; ++a) {
                float qv = sh_q[r0 + a];
                int m = (dbase + a) >> 1;
                float2 e = up2(P2[a][m]);
                if (a & 1) e.y += qv; else e.x += qv;
                P2[a][m] = pk2(e.x, e.y);
            }
        }

        // prefetch next step's y/u into registers
        const int tn = (t + 1 < TSEQ) ? t + 1 : t;
        float2 ry2 = *(const float2*)&obs[((size_t)tn * BATCH + b) * 64 + 2 * lane];
        float  ru  = ext[((size_t)(tn - 1) * BATCH + b) * 32 + lane];

        // ---- 32 blocks of 2 observations, ONE __syncwarp each ----
        #pragma unroll 1
        for (int blk = 0; blk < 32; ++blk) {
            const int o  = blk << 1;
            const int pb = blk & 1;

            // phase 1: vp partials, V reduce-scatter, z partials, Gram partials
            u64 vpp[2][4];   // packed vp over my 8 rows
            float gv[5];     // g00 g10 g11 z0 z1 (partials)
            #pragma unroll
            for (int j = 0; j < 2; ++j) {
                const ulonglong2* hp = (const ulonglong2*)&sh_H[((o + j) << 6) + c0];
                u64 h2[8];
                #pragma unroll
                for (int m = 0; m < 4; ++m) { ulonglong2 hv = hp[m]; h2[2*m] = hv.x; h2[2*m+1] = hv.y; }
                float vp[8];
                #pragma unroll
                for (int a = 0; a < 8; ++a) {
                    u64 acc = 0ull;
                    #pragma unroll
                    for (int m = 0; m < 8; ++m) ffma2(acc, P2[a][m], h2[m], acc);
                    float2 f = up2(acc);
                    vp[a] = f.x + f.y;
                }
                // pack for Gram dots
                #pragma unroll
                for (int m = 0; m < 4; ++m) vpp[j][m] = pk2(vp[2*m], vp[2*m+1]);
                // reduce-scatter 8 values over the 4-lane group (6 shfl)
                float k4[4], k2[2];
                #pragma unroll
                for (int m = 0; m < 4; ++m) {
                    float keep = bb0 ? vp[m + 4] : vp[m];
                    float send = bb0 ? vp[m]     : vp[m + 4];
                    k4[m] = keep + __shfl_xor_sync(0xffffffffu, send, 1);
                }
                #pragma unroll
                for (int m = 0; m < 2; ++m) {
                    float keep = bb1 ? k4[m + 2] : k4[m];
                    float send = bb1 ? k4[m]     : k4[m + 2];
                    k2[m] = keep + __shfl_xor_sync(0xffffffffu, send, 2);
                }
                *(float2*)&sh_V[w][pb][j][r0 + vidx] = make_float2(k2[0], k2[1]);
                // z partial over my 16 cols (replicated 8x across rg -> /8 later)
                u64 za = 0ull;
                #pragma unroll
                for (int m = 0; m < 8; ++m) ffma2(za, h2[m], muc2[m], za);
                float2 zf = up2(za);
                gv[3 + j] = zf.x + zf.y;
                // Gram partials using h row-quads over my 8 rows
                const ulonglong2* hr = (const ulonglong2*)&sh_H[((o + j) << 6) + r0];
                ulonglong2 ha = hr[0], hb = hr[1];
                u64 hq[4] = {ha.x, ha.y, hb.x, hb.y};
                #pragma unroll
                for (int k = 0; k <= j; ++k) {
                    u64 acc = 0ull;
                    ffma2(acc, hq[0], vpp[k][0], acc);
                    ffma2(acc, hq[1], vpp[k][1], acc);
                    ffma2(acc, hq[2], vpp[k][2], acc);
                    ffma2(acc, hq[3], vpp[k][3], acc);
                    float2 f = up2(acc);
                    gv[j + k + (j & k)] = f.x + f.y;   // (0,0)->0, (1,0)->1, (1,1)->3? fix below
                }
            }
            // remap: j=0,k=0 -> g00 (idx0); j=1,k=0 -> g10 (idx1); j=1,k=1 -> g11 (idx2)
            // the expression above gives idx j+k+(j&k): (0,0)=0, (1,0)=1, (1,1)=3 — wrong for g11.
            // Handled by writing directly: recompute mapping inline instead.
            // (gv[3],gv[4] are z0,z1; g11 landed in gv[3]?? -> avoid: see corrected loop below)

            // corrected Gram placement (overwrite): redo with explicit indices
            {
                // recompute cheaply is wasteful; instead we rely on a safe layout:
                // we recompute the j=1,k=1 entry index collision fix:
                // NOTE: loop above stored (1,1) into gv[3] clobbering z0.
                // To keep code simple and correct, recompute z0 here:
                const ulonglong2* hp0 = (const ulonglong2*)&sh_H[(o << 6) + c0];
                u64 za = 0ull;
                #pragma unroll
                for (int m = 0; m < 4; ++m) {
                    ulonglong2 hv = hp0[m];
                    ffma2(za, hv.x, muc2[2*m], za);
                    ffma2(za, hv.y, muc2[2*m+1], za);
                }
                float2 zf = up2(za);
                float g11v = gv[3];          // (1,1) result
                gv[2] = g11v;
                gv[3] = zf.x + zf.y;         // z0 recomputed
            }

            // 8-value butterfly reduce-scatter over lane bits 0-2, then sum octets
            {
                float val[8];
                val[0] = gv[0]; val[1] = gv[1]; val[2] = gv[2];
                val[3] = gv[3]; val[4] = gv[4];
                val[5] = 0.0f; val[6] = 0.0f; val[7] = 0.0f;
                const bool s2l = lane & 4, s1 = lane & 2, s0 = lane & 1;
                #pragma unroll
                for (int k = 0; k < 4; ++k) {
                    float keep = s2l ? val[k + 4] : val[k];
                    float send = s2l ? val[k]     : val[k + 4];
                    val[k] = keep + __shfl_xor_sync(0xffffffffu, send, 4);
                }
                #pragma unroll
                for (int k = 0; k < 2; ++k) {
                    float keep = s1 ? val[k + 2] : val[k];
                    float send = s1 ? val[k]     : val[k + 2];
                    val[k] = keep + __shfl_xor_sync(0xffffffffu, send, 2);
                }
                {
                    float keep = s0 ? val[1] : val[0];
                    float send = s0 ? val[0] : val[1];
                    val[0] = keep + __shfl_xor_sync(0xffffffffu, send, 1);
                }
                val[0] += __shfl_xor_sync(0xffffffffu, val[0], 8);
                val[0] += __shfl_xor_sync(0xffffffffu, val[0], 16);
                if (lane < 5) sh_G[w][pb][lane] = val[0];
            }
            __syncwarp();   // the ONLY sync per block

            // phase 3: 2x2 recursion (redundant per lane, exact)
            float4 gq = *(const float4*)&sh_G[w][pb][0];   // g00 g10 g11 z0
            float z1v = sh_G[w][pb][4];
            float2 yq = *(const float2*)&sh_y[w][tb][o];
            float z0v = gq.w * 0.125f;
            z1v *= 0.125f;

            float rs0 = __fdividef(1.0f, gq.x + sh_r[o + 0]);
            float c01 = gq.y * rs0;
            float rs1 = __fdividef(1.0f, (gq.z - c01 * gq.y) + sh_r[o + 1]);
            float f0 = (yq.x - z0v) * rs0;
            float f1 = (yq.y - z1v - gq.y * f0) * rs1;

            // phase 4: w col strips, mu update, pre-scale, w row strips, rank-2
            u64 wc0[8], wc1[8];
            {
                const ulonglong2* q0 = (const ulonglong2*)&sh_V[w][pb][0][c0];
                const ulonglong2* q1 = (const ulonglong2*)&sh_V[w][pb][1][c0];
                #pragma unroll
                for (int m = 0; m < 4; ++m) {
                    ulonglong2 v0 = q0[m], v1 = q1[m];
                    wc0[2*m] = v0.x; wc0[2*m+1] = v0.y;
                    wc1[2*m] = v1.x; wc1[2*m+1] = v1.y;
                }
                u64 n01 = pk2(-c01, -c01);
                #pragma unroll
                for (int m = 0; m < 8; ++m) ffma2(wc1[m], n01, wc0[m], wc1[m]);
            }
            {
                u64 f02 = pk2(f0, f0), f12 = pk2(f1, f1);
                #pragma unroll
                for (int m = 0; m < 8; ++m) {
                    ffma2(muc2[m], f02, wc0[m], muc2[m]);
                    ffma2(muc2[m], f12, wc1[m], muc2[m]);
                }
            }
            {
                u64 m0s = pk2(-rs0, -rs0), m1s = pk2(-rs1, -rs1);
                #pragma unroll
                for (int m = 0; m < 8; ++m) {
                    wc0[m] = fmul2(wc0[m], m0s);
                    wc1[m] = fmul2(wc1[m], m1s);
                }
            }
            float wr0[8], wr1[8];
            {
                float4 pa = *(const float4*)&sh_V[w][pb][0][r0];
                float4 pe = *(const float4*)&sh_V[w][pb][0][r0 + 4];
                wr0[0]=pa.x; wr0[1]=pa.y; wr0[2]=pa.z; wr0[3]=pa.w;
                wr0[4]=pe.x; wr0[5]=pe.y; wr0[6]=pe.z; wr0[7]=pe.w;
                float4 qa = *(const float4*)&sh_V[w][pb][1][r0];
                float4 qe = *(const float4*)&sh_V[w][pb][1][r0 + 4];
                wr1[0]=qa.x; wr1[1]=qa.y; wr1[2]=qa.z; wr1[3]=qa.w;
                wr1[4]=qe.x; wr1[5]=qe.y; wr1[6]=qe.z; wr1[7]=qe.w;
                #pragma unroll
                for (int a = 0; a < 8; ++a) wr1[a] -= c01 * wr0[a];
            }
            #pragma unroll
            for (int a = 0; a < 8; ++a) {
                u64 g0 = pk2(wr0[a], wr0[a]);
                u64 g1 = pk2(wr1[a], wr1[a]);
                #pragma unroll
                for (int m = 0; m < 8; ++m) {
                    ffma2(P2[a][m], g0, wc0[m], P2[a][m]);
                    ffma2(P2[a][m], g1, wc1[m], P2[a][m]);
                }
            }
        }

        // ---- outputs ; stage next step's y/u ----
        if (rg == 0) {
            float* op = &outmu[((size_t)t * BATCH + b) * 64 + c0];
            #pragma unroll
            for (int p = 0; p < 4; ++p) {
                float2 e0 = up2(muc2[2 * p]), e1 = up2(muc2[2 * p + 1]);
                *(float4*)(op + 4 * p) = make_float4(e0.x, e0.y, e1.x, e1.y);
            }
        }
        if (diag) {
            #pragma unroll
            for (int a = 0; a < 8; ++a) {
                float2 e = up2(P2[a][(dbase + a) >> 1]);
                float dv = (a & 1) ? e.y : e.x;
                outls[((size_t)t * BATCH + b) * 64 + r0 + a] = 0.5f * logf(dv);
            }
        }
        *(float2*)&sh_y[w][tb ^ 1][2 * lane] = ry2;
        sh_u[w][tb ^ 1][lane] = ru;
        __syncwarp();
    }
}

extern "C" void kernel_launch(void* const* d_in, const int* in_sizes, int n_in,
                              void* d_out, int out_size) {
    const float* ext  = (const float*)d_in[0];   // (500, 512, 32)
    const float* obs  = (const float*)d_in[1];   // (500, 512, 64)
    const float* mu0  = (const float*)d_in[2];   // (512, 64)
    const float* sg0  = (const float*)d_in[3];   // (512, 64)
    const float* lsig = (const float*)d_in[4];   // (64,)
    const float* Bm   = (const float*)d_in[5];   // (64, 32)
    const float* H    = (const float*)d_in[6];   // (64, 64)
    const float* ldel = (const float*)d_in[7];   // (64,)
    float* out = (float*)d_out;

    akf_main<<<BATCH / 4, 128>>>(ext, obs, mu0, sg0, lsig, Bm, H, ldel, out);
}